// round 13
// baseline (speedup 1.0000x reference)
#include <cuda_runtime.h>
#include <cuda_fp16.h>
#include <cmath>
#include <complex>
#include <algorithm>
#include <cstdint>

// ---------------- problem constants ----------------
#define MTOT 9        // (LMAX+1)^2
#define CCH  128      // channels
#define KNB  16       // neighbors
#define HH   8        // heads
#define MAXN 4096     // max nodes (matches setup)

struct W3J { float v[210]; };

// ---------------- scratch (static device globals; no allocation) ----------------
__device__ __half g_h1f16[MAXN * MTOT * CCH];      // fp16 gather payload [n][m][c]
__device__ __half g_cdhi [MAXN * MTOT * CCH];      // gather output hi plane, GEMM-row layout
__device__ __half g_cdlo [MAXN * MTOT * CCH];      // gather output lo plane
__device__ __half g_Whi[2 * 3 * CCH * CCH];        // transposed: [which][l][d_out][c_in]

// ======================================================================
// Host-side real Wigner-3j construction (port of the e3nn-style reference)
// ======================================================================
static double hfact(int n){ double r=1.0; for(int i=2;i<=n;i++) r*= (double)i; return r; }

static double su2_cg(int j1,int j2,int j3,int m1,int m2,int m3){
  if(m3 != m1+m2) return 0.0;
  if(j3 < std::abs(j1-j2) || j3 > j1+j2) return 0.0;
  double pref = std::sqrt((2.0*j3+1.0)*hfact(j1+j2-j3)*hfact(j1-j2+j3)*hfact(-j1+j2+j3)/hfact(j1+j2+j3+1));
  pref *= std::sqrt(hfact(j3+m3)*hfact(j3-m3)*hfact(j1-m1)*hfact(j1+m1)*hfact(j2-m2)*hfact(j2+m2));
  int vmin = std::max(0, std::max(j2-j3-m1, j1-j3+m2));
  int vmax = std::min(j1+j2-j3, std::min(j1-m1, j2+m2));
  double s=0.0;
  for(int v=vmin; v<=vmax; v++){
    double den = hfact(v)*hfact(j1+j2-j3-v)*hfact(j1-m1-v)*hfact(j2+m2-v)*hfact(j3-j2+m1+v)*hfact(j3-j1-m2+v);
    s += ((v&1)? -1.0 : 1.0)/den;
  }
  return pref*s;
}

static void q_r2c(int l, std::complex<double>* q){
  int n = 2*l+1;
  for(int i=0;i<n*n;i++) q[i]=std::complex<double>(0.0,0.0);
  double is2 = 1.0/std::sqrt(2.0);
  for(int m=-l;m<0;m++){
    q[(l+m)*n + (l-m)] = std::complex<double>(is2, 0.0);
    q[(l+m)*n + (l+m)] = std::complex<double>(0.0,-is2);
  }
  q[l*n + l] = std::complex<double>(1.0,0.0);
  for(int m=1;m<=l;m++){
    double sg = (m&1)? -1.0 : 1.0;
    q[(l+m)*n + (l+m)] = std::complex<double>(sg*is2, 0.0);
    q[(l+m)*n + (l-m)] = std::complex<double>(0.0, sg*is2);
  }
  std::complex<double> f(1.0,0.0), mi(0.0,-1.0);
  for(int i=0;i<l;i++) f *= mi;
  for(int i=0;i<n*n;i++) q[i] *= f;
}

static void real_w3j(int l1, int l3, float* out){
  const int n1=2*l1+1, n2=3, n3=2*l3+1;
  std::complex<double> Cc[5*3*5];
  for(int i=0;i<n1;i++) for(int j=0;j<n2;j++) for(int k=0;k<n3;k++)
    Cc[(i*n2+j)*n3+k] = std::complex<double>(su2_cg(l1,1,l3, i-l1, j-1, k-l3), 0.0);
  std::complex<double> Q1[25],Q2[9],Q3[25];
  q_r2c(l1,Q1); q_r2c(1,Q2); q_r2c(l3,Q3);
  std::complex<double> C[5*3*5];
  for(int a=0;a<n1;a++) for(int b=0;b<n2;b++) for(int c=0;c<n3;c++){
    std::complex<double> s(0.0,0.0);
    for(int i=0;i<n1;i++) for(int j=0;j<n2;j++) for(int k=0;k<n3;k++)
      s += Q1[i*n1+a]*Q2[j*n2+b]*std::conj(Q3[k*n3+c])*Cc[(i*n2+j)*n3+k];
    C[(a*n2+b)*n3+c]=s;
  }
  double sr=0.0, si=0.0;
  for(int i=0;i<n1*n2*n3;i++){ sr += std::fabs(C[i].real()); si += std::fabs(C[i].imag()); }
  double vals[75]; double norm=0.0;
  for(int i=0;i<n1*n2*n3;i++){ double v=(sr>=si)? C[i].real() : C[i].imag(); vals[i]=v; norm+=v*v; }
  norm = std::sqrt(norm);
  double sc = std::sqrt((double)(2*l3+1))/norm;
  for(int i=0;i<n1*n2*n3;i++) out[i] = (float)(vals[i]*sc);
}

static void build_w3j(W3J* w){
  real_w3j(0,1, w->v+0);
  real_w3j(1,0, w->v+9);
  real_w3j(1,1, w->v+18);
  real_w3j(1,2, w->v+45);
  real_w3j(2,1, w->v+90);
  real_w3j(2,2, w->v+135);
}

// ======================================================================
// Row mapping: GEMM rows grouped by degree.
// ======================================================================
__device__ __forceinline__ void row_to_nm(int R, int N, int& n, int& m){
  if(R < N){ n = R; m = 0; }
  else if(R < 4*N){ int q = R - N; n = q/3; m = 1 + q%3; }
  else { int q = R - 4*N; n = q/5; m = 4 + q%5; }
}

__device__ __forceinline__ uint32_t smem_u32(const void* p){
  uint32_t a;
  asm("{ .reg .u64 t; cvta.to.shared.u64 t, %1; cvt.u32.u64 %0, t; }" : "=r"(a) : "l"(p));
  return a;
}

// ======================================================================
// W conversion: W[l][c][d] fp32 -> transposed fp16 Wt[which][l][d][c]
// ======================================================================
__global__ __launch_bounds__(256)
void conv_w_kernel(const float* __restrict__ w1, const float* __restrict__ w2,
                   __half* __restrict__ Whi)
{
  int t = blockIdx.x*256 + threadIdx.x;
  if(t >= 2*3*CCH*CCH) return;
  int which = t / (3*CCH*CCH);
  int rem = t % (3*CCH*CCH);
  int l = rem / (CCH*CCH);
  int e = rem % (CCH*CCH);
  int d = e >> 7, c = e & 127;
  const float* w = which ? w2 : w1;
  Whi[t] = __float2half_rn(w[((size_t)l*CCH + c)*CCH + d]);
}

// ======================================================================
// HMMA GEMM common pieces
// ======================================================================
#define PADC 136                        // padded smem row stride in halves (272B)

__device__ __forceinline__ void mma16816(float* c, const uint32_t* a, const uint32_t* b){
  asm volatile("mma.sync.aligned.m16n8k16.row.col.f32.f16.f16.f32 "
               "{%0,%1,%2,%3}, {%4,%5,%6,%7}, {%8,%9}, {%0,%1,%2,%3};"
               : "+f"(c[0]), "+f"(c[1]), "+f"(c[2]), "+f"(c[3])
               : "r"(a[0]), "r"(a[1]), "r"(a[2]), "r"(a[3]), "r"(b[0]), "r"(b[1]));
}

#define LDSM4(r, addr) \
  asm volatile("ldmatrix.sync.aligned.m8n8.x4.shared.b16 {%0,%1,%2,%3}, [%4];" \
               : "=r"((r)[0]), "=r"((r)[1]), "=r"((r)[2]), "=r"((r)[3]) : "r"(addr))

#define CP_ASYNC16(dst, src) \
  asm volatile("cp.async.ca.shared.global [%0], [%1], 16;" :: "r"(dst), "l"(src))

// ======================================================================
// GEMM1: single-term fp16 (A_hi * W_hi), output fp16 only. [R10 version]
// ======================================================================
#define G1_OFF_A 0
#define G1_OFF_W (128*PADC*2)            // 34816
#define G1_OFF_BIAS (2*128*PADC*2)       // 69632
#define G1_SMEM (G1_OFF_BIAS + 512)      // 70144

__global__ __launch_bounds__(512, 2)
void gemm1_kernel(const float* __restrict__ x, const __half* __restrict__ Whi,
                  const float* __restrict__ bias, __half* __restrict__ out16, int N)
{
  extern __shared__ char smem[];
  const uint32_t sb = smem_u32(smem);
  const int tid = threadIdx.x;
  const int wid = tid >> 5, lane = tid & 31;
  const int tile = blockIdx.x;
  const int rows = 9*N;
  const int t0 = N >> 7, t1 = t0*4;
  const int l = (tile < t0) ? 0 : ((tile < t1) ? 1 : 2);

  { // async stage W[l]
    const char* srcH = (const char*)(Whi + (size_t)l*CCH*CCH);
    #pragma unroll
    for(int i=0;i<4;i++){
      int j = tid + i*512;
      int row = j >> 4, chunk = j & 15;
      CP_ASYNC16(sb + G1_OFF_W + row*(PADC*2) + chunk*16, srcH + row*256 + chunk*16);
    }
    asm volatile("cp.async.commit_group;");
  }
  if(tid < 128) *reinterpret_cast<float*>(smem + G1_OFF_BIAS + tid*4) = bias[tid];

  // stage A (fp32 -> fp16 hi, padded)
  #pragma unroll
  for(int i=0;i<8;i++){
    int j = tid + i*512;
    int row = j >> 5, col4 = j & 31;
    int R = tile*128 + row;
    float4 v = make_float4(0.f,0.f,0.f,0.f);
    if(R < rows){
      int n, m; row_to_nm(R, N, n, m);
      v = reinterpret_cast<const float4*>(x)[ ((size_t)n*MTOT + m)*32 + col4 ];
    }
    uint2 hp;
    hp.x = __half_as_ushort(__float2half_rn(v.x)) | ((uint32_t)__half_as_ushort(__float2half_rn(v.y)) << 16);
    hp.y = __half_as_ushort(__float2half_rn(v.z)) | ((uint32_t)__half_as_ushort(__float2half_rn(v.w)) << 16);
    *reinterpret_cast<uint2*>(smem + G1_OFF_A + row*(PADC*2) + col4*8) = hp;
  }
  asm volatile("cp.async.wait_group 0;");
  __syncthreads();

  const int mrow0 = (wid >> 1)*16, ncol0 = (wid & 1)*64;
  const int g = lane >> 2, t = lane & 3;
  const int lr = lane & 7, aw = lane >> 3;
  const uint32_t aBase = sb + G1_OFF_A + (mrow0 + lr + (aw & 1)*8)*(PADC*2) + ((aw >> 1)*8)*2;
  const uint32_t bBase = sb + G1_OFF_W + (ncol0 + ((lane >> 4) << 3) + lr)*(PADC*2) + (((lane >> 3) & 1)*8)*2;

  float acc[32];
  #pragma unroll
  for(int i=0;i<32;i++) acc[i] = 0.f;

  #pragma unroll
  for(int ks=0; ks<8; ks++){
    const uint32_t ko = ks*32;
    uint32_t aH[4];
    LDSM4(aH, aBase + ko);
    #pragma unroll
    for(int ntp=0; ntp<4; ntp++){
      uint32_t bH[4];
      LDSM4(bH, bBase + ntp*16*(PADC*2) + ko);
      mma16816(acc + (2*ntp  )*4, aH, bH);
      mma16816(acc + (2*ntp+1)*4, aH, bH+2);
    }
  }

  const float* sbias = reinterpret_cast<const float*>(smem + G1_OFF_BIAS);
  #pragma unroll
  for(int half=0; half<2; half++){
    const int R = tile*128 + mrow0 + g + half*8;
    if(R >= rows) continue;
    int n, m; row_to_nm(R, N, n, m);
    __half2* po16 = reinterpret_cast<__half2*>(out16 + ((size_t)n*MTOT + m)*CCH + ncol0);
    #pragma unroll
    for(int nt=0; nt<8; nt++){
      const int c0 = nt*8 + 2*t;
      float v0 = acc[nt*4 + half*2 + 0];
      float v1 = acc[nt*4 + half*2 + 1];
      if(m == 0){ v0 += sbias[ncol0 + c0]; v1 += sbias[ncol0 + c0 + 1]; }
      po16[c0 >> 1] = __floats2half2_rn(v0, v1);
    }
  }
}

// ======================================================================
// GEMM2: two-term split-A ((A_hi + A_lo) * W_hi), pre-split planes,
// pure cp.async staging. [R10 version]
// ======================================================================
#define G2_OFF_AH 0
#define G2_OFF_AL (128*PADC*2)            // 34816
#define G2_OFF_W  (2*128*PADC*2)          // 69632
#define G2_OFF_BIAS (3*128*PADC*2)        // 104448
#define G2_SMEM (G2_OFF_BIAS + 512)       // 104960

__global__ __launch_bounds__(512, 2)
void gemm2_kernel(const __half* __restrict__ Ahi, const __half* __restrict__ Alo,
                  const __half* __restrict__ Whi, const float* __restrict__ bias,
                  float* __restrict__ out, int N)
{
  extern __shared__ char smem[];
  const uint32_t sb = smem_u32(smem);
  const int tid = threadIdx.x;
  const int wid = tid >> 5, lane = tid & 31;
  const int tile = blockIdx.x;
  const int rows = 9*N;
  const int t0 = N >> 7, t1 = t0*4;
  const int l = (tile < t0) ? 0 : ((tile < t1) ? 1 : 2);

  { // async stage: W[l] + A hi/lo planes (all contiguous copies)
    const char* srcW = (const char*)(Whi + (size_t)l*CCH*CCH);
    const char* srcH = (const char*)(Ahi + (size_t)tile*128*CCH);
    const char* srcL = (const char*)(Alo + (size_t)tile*128*CCH);
    #pragma unroll
    for(int i=0;i<4;i++){
      int j = tid + i*512;                 // 2048 chunks = 128 rows x 16
      int row = j >> 4, chunk = j & 15;
      CP_ASYNC16(sb + G2_OFF_W  + row*(PADC*2) + chunk*16, srcW + row*256 + chunk*16);
      CP_ASYNC16(sb + G2_OFF_AH + row*(PADC*2) + chunk*16, srcH + row*256 + chunk*16);
      CP_ASYNC16(sb + G2_OFF_AL + row*(PADC*2) + chunk*16, srcL + row*256 + chunk*16);
    }
    asm volatile("cp.async.commit_group;");
  }
  if(tid < 128) *reinterpret_cast<float*>(smem + G2_OFF_BIAS + tid*4) = bias[tid];
  asm volatile("cp.async.wait_group 0;");
  __syncthreads();

  const int mrow0 = (wid >> 1)*16, ncol0 = (wid & 1)*64;
  const int g = lane >> 2, t = lane & 3;
  const int lr = lane & 7, aw = lane >> 3;
  const uint32_t aoff = (mrow0 + lr + (aw & 1)*8)*(PADC*2) + ((aw >> 1)*8)*2;
  const uint32_t aHBase = sb + G2_OFF_AH + aoff;
  const uint32_t aLBase = sb + G2_OFF_AL + aoff;
  const uint32_t bBase  = sb + G2_OFF_W + (ncol0 + ((lane >> 4) << 3) + lr)*(PADC*2) + (((lane >> 3) & 1)*8)*2;

  float acc[32];
  #pragma unroll
  for(int i=0;i<32;i++) acc[i] = 0.f;

  #pragma unroll
  for(int ks=0; ks<8; ks++){
    const uint32_t ko = ks*32;
    uint32_t aH[4], aL[4];
    LDSM4(aH, aHBase + ko);
    LDSM4(aL, aLBase + ko);
    #pragma unroll
    for(int ntp=0; ntp<4; ntp++){
      uint32_t bH[4];
      LDSM4(bH, bBase + ntp*16*(PADC*2) + ko);
      mma16816(acc + (2*ntp  )*4, aH, bH);
      mma16816(acc + (2*ntp  )*4, aL, bH);
      mma16816(acc + (2*ntp+1)*4, aH, bH+2);
      mma16816(acc + (2*ntp+1)*4, aL, bH+2);
    }
  }

  const float* sbias = reinterpret_cast<const float*>(smem + G2_OFF_BIAS);
  #pragma unroll
  for(int half=0; half<2; half++){
    const int R = tile*128 + mrow0 + g + half*8;
    if(R >= rows) continue;
    int n, m; row_to_nm(R, N, n, m);
    float pn = (m==0) ? 1.0f : ((m<4) ? 0.57735026918962576f : 0.70710678118654752f);
    float* po = out + ((size_t)n*MTOT + m)*CCH + ncol0;
    #pragma unroll
    for(int nt=0; nt<8; nt++){
      const int c0 = nt*8 + 2*t;
      float v0 = acc[nt*4 + half*2 + 0];
      float v1 = acc[nt*4 + half*2 + 1];
      if(m == 0){ v0 += sbias[ncol0 + c0]; v1 += sbias[ncol0 + c0 + 1]; }
      *reinterpret_cast<float2*>(po + c0) = make_float2(v0*pn, v1*pn);
    }
  }
}

// ======================================================================
// Device: contract accumulated outer-product tensor P with w3j + tpw.
// ======================================================================
__device__ __forceinline__ void contract_point(const float* p0, const float* p1, const float* p2,
                                               const float* tpw, const W3J& w, float* o){
  #pragma unroll
  for(int m=0;m<MTOT;m++) o[m]=0.0f;
  #pragma unroll
  for(int c=0;c<3;c++){
    float t=0.f;
    #pragma unroll
    for(int b=0;b<3;b++) t = fmaf(w.v[0 + b*3 + c], p0[b], t);
    o[1+c] = fmaf(tpw[0], t, o[1+c]);
  }
  {
    float t=0.f;
    #pragma unroll
    for(int a=0;a<3;a++)
      #pragma unroll
      for(int b=0;b<3;b++) t = fmaf(w.v[9 + a*3 + b], p1[a*3+b], t);
    o[0] = fmaf(tpw[1], t, o[0]);
  }
  #pragma unroll
  for(int c=0;c<3;c++){
    float t=0.f;
    #pragma unroll
    for(int a=0;a<3;a++)
      #pragma unroll
      for(int b=0;b<3;b++) t = fmaf(w.v[18 + (a*3+b)*3 + c], p1[a*3+b], t);
    o[1+c] = fmaf(tpw[2], t, o[1+c]);
  }
  #pragma unroll
  for(int c=0;c<5;c++){
    float t=0.f;
    #pragma unroll
    for(int a=0;a<3;a++)
      #pragma unroll
      for(int b=0;b<3;b++) t = fmaf(w.v[45 + (a*3+b)*5 + c], p1[a*3+b], t);
    o[4+c] = fmaf(tpw[3], t, o[4+c]);
  }
  #pragma unroll
  for(int c=0;c<3;c++){
    float t=0.f;
    #pragma unroll
    for(int a=0;a<5;a++)
      #pragma unroll
      for(int b=0;b<3;b++) t = fmaf(w.v[90 + (a*3+b)*3 + c], p2[a*3+b], t);
    o[1+c] = fmaf(tpw[4], t, o[1+c]);
  }
  #pragma unroll
  for(int c=0;c<5;c++){
    float t=0.f;
    #pragma unroll
    for(int a=0;a<5;a++)
      #pragma unroll
      for(int b=0;b<3;b++) t = fmaf(w.v[135 + (a*3+b)*5 + c], p2[a*3+b], t);
    o[4+c] = fmaf(tpw[5], t, o[4+c]);
  }
}

// ======================================================================
// Fully fused gather with split-K over neighbors:
// 128 threads/node = 2 groups x 64 threads (2 channels each).
// group 1 accumulates neighbors 8-15 and spills P to smem; group 0
// accumulates 0-7, adds partials, contracts, writes split-fp16 planes.
// ======================================================================
__global__ __launch_bounds__(256)
void gather_kernel(const __half* __restrict__ h1f,
                   const float* __restrict__ pos, const float* __restrict__ exp_pos,
                   const float* __restrict__ alpha, const int* __restrict__ idx,
                   const float* __restrict__ tp_w,
                   __half* __restrict__ cdhi, __half* __restrict__ cdlo,
                   int N1, W3J w, float scale)
{
  __shared__ float2 sP[2][27][64];           // [node-in-block][P index][thread]
  const int nodeLoc = threadIdx.x >> 7;      // 0..1
  const int b = blockIdx.x*2 + nodeLoc;
  const int grp = (threadIdx.x >> 6) & 1;    // neighbor split group
  const int t = threadIdx.x & 63;
  const int c0 = 2*t;
  const int h = c0 >> 4;
  const bool valid = (b < N1);

  float2 P[MTOT][3];
  #pragma unroll
  for(int m=0;m<MTOT;m++)
    #pragma unroll
    for(int k=0;k<3;k++) P[m][k] = make_float2(0.f, 0.f);

  if(valid){
    float yb[3];
    #pragma unroll
    for(int k=0;k<3;k++) yb[k] = scale * pos[b*3+k];

    const int*   ib = idx   + (size_t)b*KNB + grp*8;
    const float* ab = alpha + (size_t)b*KNB*HH + grp*8*HH;

    #pragma unroll 2
    for(int j=0;j<8;j++){
      const int n = ib[j];
      const float a = ab[j*HH + h];
      float ady[3];
      #pragma unroll
      for(int k=0;k<3;k++) ady[k] = a * (yb[k] - scale * exp_pos[n*3+k]);
      const __half2* px = reinterpret_cast<const __half2*>(h1f + (size_t)n*MTOT*CCH) + t;
      #pragma unroll
      for(int m=0;m<MTOT;m++){
        float2 v = __half22float2(px[m*64]);
        #pragma unroll
        for(int k=0;k<3;k++){
          P[m][k].x = fmaf(v.x, ady[k], P[m][k].x);
          P[m][k].y = fmaf(v.y, ady[k], P[m][k].y);
        }
      }
    }
  }

  // group 1 spills partial P
  if(grp == 1){
    #pragma unroll
    for(int m=0;m<MTOT;m++)
      #pragma unroll
      for(int k=0;k<3;k++) sP[nodeLoc][m*3+k][t] = P[m][k];
  }
  __syncthreads();

  if(grp == 0 && valid){
    #pragma unroll
    for(int m=0;m<MTOT;m++)
      #pragma unroll
      for(int k=0;k<3;k++){
        float2 q = sP[nodeLoc][m*3+k][t];
        P[m][k].x += q.x;  P[m][k].y += q.y;
      }

    float tpw0[6], tpw1[6];
    #pragma unroll
    for(int p=0;p<6;p++){
      float2 v = *reinterpret_cast<const float2*>(tp_w + p*CCH + c0);
      tpw0[p] = v.x; tpw1[p] = v.y;
    }

    float p0[3], p1[9], p2[15], o0[MTOT], o1[MTOT];
    #pragma unroll
    for(int k=0;k<3;k++) p0[k] = P[0][k].x;
    #pragma unroll
    for(int a2=0;a2<3;a2++)
      #pragma unroll
      for(int k=0;k<3;k++) p1[a2*3+k] = P[1+a2][k].x;
    #pragma unroll
    for(int a2=0;a2<5;a2++)
      #pragma unroll
      for(int k=0;k<3;k++) p2[a2*3+k] = P[4+a2][k].x;
    contract_point(p0, p1, p2, tpw0, w, o0);
    #pragma unroll
    for(int k=0;k<3;k++) p0[k] = P[0][k].y;
    #pragma unroll
    for(int a2=0;a2<3;a2++)
      #pragma unroll
      for(int k=0;k<3;k++) p1[a2*3+k] = P[1+a2][k].y;
    #pragma unroll
    for(int a2=0;a2<5;a2++)
      #pragma unroll
      for(int k=0;k<3;k++) p2[a2*3+k] = P[4+a2][k].y;
    contract_point(p0, p1, p2, tpw1, w, o1);

    // write split-fp16 planes in GEMM-row layout (half2 per plane per m)
    #pragma unroll
    for(int m=0;m<MTOT;m++){
      int R = (m==0) ? b : ((m<4) ? (N1 + b*3 + (m-1)) : (4*N1 + b*5 + (m-4)));
      __half2 hi2 = __floats2half2_rn(o0[m], o1[m]);
      float2 hf = __half22float2(hi2);
      __half2 lo2 = __floats2half2_rn(o0[m] - hf.x, o1[m] - hf.y);
      *reinterpret_cast<__half2*>(cdhi + (size_t)R*CCH + c0) = hi2;
      *reinterpret_cast<__half2*>(cdlo + (size_t)R*CCH + c0) = lo2;
    }
  }
}

// ======================================================================
// launch
// ======================================================================
extern "C" void kernel_launch(void* const* d_in, const int* in_sizes, int n_in,
                              void* d_out, int out_size)
{
  const float* pos     = (const float*)d_in[0];
  const float* exp_pos = (const float*)d_in[1];
  // d_in[2] = h : unused by the reference
  const float* exp_h   = (const float*)d_in[3];
  const float* alpha   = (const float*)d_in[4];
  const int*   idx     = (const int*)  d_in[5];
  const float* w1w     = (const float*)d_in[6];
  const float* w1b     = (const float*)d_in[7];
  const float* w2w     = (const float*)d_in[8];
  const float* w2b     = (const float*)d_in[9];
  const float* tpw     = (const float*)d_in[10];

  const int N1 = in_sizes[0]/3;
  const int N2 = in_sizes[1]/3;

  W3J w;
  build_w3j(&w);
  const double PI = 3.14159265358979323846;
  const float scale = (float)(2.04665350914 * std::sqrt(3.0/(4.0*PI)));  // COEF1 * SH1_INT

  __half *p_h1f=nullptr, *p_whi=nullptr, *p_cdh=nullptr, *p_cdl=nullptr;
  cudaGetSymbolAddress((void**)&p_h1f, g_h1f16);
  cudaGetSymbolAddress((void**)&p_whi, g_Whi);
  cudaGetSymbolAddress((void**)&p_cdh, g_cdhi);
  cudaGetSymbolAddress((void**)&p_cdl, g_cdlo);

  cudaFuncSetAttribute(gemm1_kernel, cudaFuncAttributeMaxDynamicSharedMemorySize, G1_SMEM);
  cudaFuncSetAttribute(gemm2_kernel, cudaFuncAttributeMaxDynamicSharedMemorySize, G2_SMEM);

  const int tiles2 = (9*N2 + 127) >> 7;   // 288 for N2=4096
  const int tiles1 = (9*N1 + 127) >> 7;

  // 0) W images (both linears, fp16, transposed)
  conv_w_kernel<<<(2*3*CCH*CCH + 255)/256, 256>>>(w1w, w2w, p_whi);
  // 1) h1f16 = fp16( so3_linear(exp_h, w1) )
  gemm1_kernel<<<tiles2, 512, G1_SMEM>>>(exp_h, p_whi, w1b, p_h1f, N2);
  // 2) fused gather (split-K over neighbors) -> split-fp16 planes
  gather_kernel<<<(N1+1)/2, 256>>>(p_h1f, pos, exp_pos, alpha, idx, tpw, p_cdh, p_cdl, N1, w, scale);
  // 3) out = so3_linear(cdiff, w2) * PATH_NORM
  gemm2_kernel<<<tiles1, 512, G2_SMEM>>>(p_cdh, p_cdl, p_whi + 3*CCH*CCH, w2b, (float*)d_out, N1);
}

// round 14
// speedup vs baseline: 1.1910x; 1.1910x over previous
#include <cuda_runtime.h>
#include <cuda_fp16.h>
#include <cmath>
#include <complex>
#include <algorithm>
#include <cstdint>

// ---------------- problem constants ----------------
#define MTOT 9        // (LMAX+1)^2
#define CCH  128      // channels
#define KNB  16       // neighbors
#define HH   8        // heads
#define MAXN 4096     // max nodes (matches setup)

struct W3J { float v[210]; };

// ---------------- scratch (static device globals; no allocation) ----------------
__device__ __half g_h1f16[MAXN * MTOT * CCH];      // fp16 gather payload [n][m][c]
__device__ __half g_cdhi [MAXN * MTOT * CCH];      // gather output hi plane, GEMM-row layout
__device__ __half g_cdlo [MAXN * MTOT * CCH];      // gather output lo plane
__device__ __half g_Whi[2 * 3 * CCH * CCH];        // transposed: [which][l][d_out][c_in]
__device__ float4 g_epos4[MAXN];                   // scale * exp_pos, packed

// ======================================================================
// Host-side real Wigner-3j construction (port of the e3nn-style reference)
// ======================================================================
static double hfact(int n){ double r=1.0; for(int i=2;i<=n;i++) r*= (double)i; return r; }

static double su2_cg(int j1,int j2,int j3,int m1,int m2,int m3){
  if(m3 != m1+m2) return 0.0;
  if(j3 < std::abs(j1-j2) || j3 > j1+j2) return 0.0;
  double pref = std::sqrt((2.0*j3+1.0)*hfact(j1+j2-j3)*hfact(j1-j2+j3)*hfact(-j1+j2+j3)/hfact(j1+j2+j3+1));
  pref *= std::sqrt(hfact(j3+m3)*hfact(j3-m3)*hfact(j1-m1)*hfact(j1+m1)*hfact(j2-m2)*hfact(j2+m2));
  int vmin = std::max(0, std::max(j2-j3-m1, j1-j3+m2));
  int vmax = std::min(j1+j2-j3, std::min(j1-m1, j2+m2));
  double s=0.0;
  for(int v=vmin; v<=vmax; v++){
    double den = hfact(v)*hfact(j1+j2-j3-v)*hfact(j1-m1-v)*hfact(j2+m2-v)*hfact(j3-j2+m1+v)*hfact(j3-j1-m2+v);
    s += ((v&1)? -1.0 : 1.0)/den;
  }
  return pref*s;
}

static void q_r2c(int l, std::complex<double>* q){
  int n = 2*l+1;
  for(int i=0;i<n*n;i++) q[i]=std::complex<double>(0.0,0.0);
  double is2 = 1.0/std::sqrt(2.0);
  for(int m=-l;m<0;m++){
    q[(l+m)*n + (l-m)] = std::complex<double>(is2, 0.0);
    q[(l+m)*n + (l+m)] = std::complex<double>(0.0,-is2);
  }
  q[l*n + l] = std::complex<double>(1.0,0.0);
  for(int m=1;m<=l;m++){
    double sg = (m&1)? -1.0 : 1.0;
    q[(l+m)*n + (l+m)] = std::complex<double>(sg*is2, 0.0);
    q[(l+m)*n + (l-m)] = std::complex<double>(0.0, sg*is2);
  }
  std::complex<double> f(1.0,0.0), mi(0.0,-1.0);
  for(int i=0;i<l;i++) f *= mi;
  for(int i=0;i<n*n;i++) q[i] *= f;
}

static void real_w3j(int l1, int l3, float* out){
  const int n1=2*l1+1, n2=3, n3=2*l3+1;
  std::complex<double> Cc[5*3*5];
  for(int i=0;i<n1;i++) for(int j=0;j<n2;j++) for(int k=0;k<n3;k++)
    Cc[(i*n2+j)*n3+k] = std::complex<double>(su2_cg(l1,1,l3, i-l1, j-1, k-l3), 0.0);
  std::complex<double> Q1[25],Q2[9],Q3[25];
  q_r2c(l1,Q1); q_r2c(1,Q2); q_r2c(l3,Q3);
  std::complex<double> C[5*3*5];
  for(int a=0;a<n1;a++) for(int b=0;b<n2;b++) for(int c=0;c<n3;c++){
    std::complex<double> s(0.0,0.0);
    for(int i=0;i<n1;i++) for(int j=0;j<n2;j++) for(int k=0;k<n3;k++)
      s += Q1[i*n1+a]*Q2[j*n2+b]*std::conj(Q3[k*n3+c])*Cc[(i*n2+j)*n3+k];
    C[(a*n2+b)*n3+c]=s;
  }
  double sr=0.0, si=0.0;
  for(int i=0;i<n1*n2*n3;i++){ sr += std::fabs(C[i].real()); si += std::fabs(C[i].imag()); }
  double vals[75]; double norm=0.0;
  for(int i=0;i<n1*n2*n3;i++){ double v=(sr>=si)? C[i].real() : C[i].imag(); vals[i]=v; norm+=v*v; }
  norm = std::sqrt(norm);
  double sc = std::sqrt((double)(2*l3+1))/norm;
  for(int i=0;i<n1*n2*n3;i++) out[i] = (float)(vals[i]*sc);
}

static void build_w3j(W3J* w){
  real_w3j(0,1, w->v+0);
  real_w3j(1,0, w->v+9);
  real_w3j(1,1, w->v+18);
  real_w3j(1,2, w->v+45);
  real_w3j(2,1, w->v+90);
  real_w3j(2,2, w->v+135);
}

// ======================================================================
// Row mapping: GEMM rows grouped by degree.
// ======================================================================
__device__ __forceinline__ void row_to_nm(int R, int N, int& n, int& m){
  if(R < N){ n = R; m = 0; }
  else if(R < 4*N){ int q = R - N; n = q/3; m = 1 + q%3; }
  else { int q = R - 4*N; n = q/5; m = 4 + q%5; }
}

__device__ __forceinline__ uint32_t smem_u32(const void* p){
  uint32_t a;
  asm("{ .reg .u64 t; cvta.to.shared.u64 t, %1; cvt.u32.u64 %0, t; }" : "=r"(a) : "l"(p));
  return a;
}

// ======================================================================
// W conversion + scaled exp_pos packing
// ======================================================================
__global__ __launch_bounds__(256)
void conv_w_kernel(const float* __restrict__ w1, const float* __restrict__ w2,
                   __half* __restrict__ Whi,
                   const float* __restrict__ exp_pos, float4* __restrict__ epos4,
                   int N2, float scale)
{
  int t = blockIdx.x*256 + threadIdx.x;
  if(t < N2){
    epos4[t] = make_float4(scale*exp_pos[t*3+0], scale*exp_pos[t*3+1], scale*exp_pos[t*3+2], 0.f);
  }
  if(t >= 2*3*CCH*CCH) return;
  int which = t / (3*CCH*CCH);
  int rem = t % (3*CCH*CCH);
  int l = rem / (CCH*CCH);
  int e = rem % (CCH*CCH);
  int d = e >> 7, c = e & 127;
  const float* w = which ? w2 : w1;
  Whi[t] = __float2half_rn(w[((size_t)l*CCH + c)*CCH + d]);
}

// ======================================================================
// HMMA GEMM common pieces
// ======================================================================
#define PADC 136                        // padded smem row stride in halves (272B)

__device__ __forceinline__ void mma16816(float* c, const uint32_t* a, const uint32_t* b){
  asm volatile("mma.sync.aligned.m16n8k16.row.col.f32.f16.f16.f32 "
               "{%0,%1,%2,%3}, {%4,%5,%6,%7}, {%8,%9}, {%0,%1,%2,%3};"
               : "+f"(c[0]), "+f"(c[1]), "+f"(c[2]), "+f"(c[3])
               : "r"(a[0]), "r"(a[1]), "r"(a[2]), "r"(a[3]), "r"(b[0]), "r"(b[1]));
}

#define LDSM4(r, addr) \
  asm volatile("ldmatrix.sync.aligned.m8n8.x4.shared.b16 {%0,%1,%2,%3}, [%4];" \
               : "=r"((r)[0]), "=r"((r)[1]), "=r"((r)[2]), "=r"((r)[3]) : "r"(addr))

#define CP_ASYNC16(dst, src) \
  asm volatile("cp.async.ca.shared.global [%0], [%1], 16;" :: "r"(dst), "l"(src))

// ======================================================================
// GEMM1: single-term fp16 (A_hi * W_hi), output fp16 only. [R10 version]
// ======================================================================
#define G1_OFF_A 0
#define G1_OFF_W (128*PADC*2)            // 34816
#define G1_OFF_BIAS (2*128*PADC*2)       // 69632
#define G1_SMEM (G1_OFF_BIAS + 512)      // 70144

__global__ __launch_bounds__(512, 2)
void gemm1_kernel(const float* __restrict__ x, const __half* __restrict__ Whi,
                  const float* __restrict__ bias, __half* __restrict__ out16, int N)
{
  extern __shared__ char smem[];
  const uint32_t sb = smem_u32(smem);
  const int tid = threadIdx.x;
  const int wid = tid >> 5, lane = tid & 31;
  const int tile = blockIdx.x;
  const int rows = 9*N;
  const int t0 = N >> 7, t1 = t0*4;
  const int l = (tile < t0) ? 0 : ((tile < t1) ? 1 : 2);

  { // async stage W[l]
    const char* srcH = (const char*)(Whi + (size_t)l*CCH*CCH);
    #pragma unroll
    for(int i=0;i<4;i++){
      int j = tid + i*512;
      int row = j >> 4, chunk = j & 15;
      CP_ASYNC16(sb + G1_OFF_W + row*(PADC*2) + chunk*16, srcH + row*256 + chunk*16);
    }
    asm volatile("cp.async.commit_group;");
  }
  if(tid < 128) *reinterpret_cast<float*>(smem + G1_OFF_BIAS + tid*4) = bias[tid];

  // stage A (fp32 -> fp16 hi, padded)
  #pragma unroll
  for(int i=0;i<8;i++){
    int j = tid + i*512;
    int row = j >> 5, col4 = j & 31;
    int R = tile*128 + row;
    float4 v = make_float4(0.f,0.f,0.f,0.f);
    if(R < rows){
      int n, m; row_to_nm(R, N, n, m);
      v = reinterpret_cast<const float4*>(x)[ ((size_t)n*MTOT + m)*32 + col4 ];
    }
    uint2 hp;
    hp.x = __half_as_ushort(__float2half_rn(v.x)) | ((uint32_t)__half_as_ushort(__float2half_rn(v.y)) << 16);
    hp.y = __half_as_ushort(__float2half_rn(v.z)) | ((uint32_t)__half_as_ushort(__float2half_rn(v.w)) << 16);
    *reinterpret_cast<uint2*>(smem + G1_OFF_A + row*(PADC*2) + col4*8) = hp;
  }
  asm volatile("cp.async.wait_group 0;");
  __syncthreads();

  const int mrow0 = (wid >> 1)*16, ncol0 = (wid & 1)*64;
  const int g = lane >> 2, t = lane & 3;
  const int lr = lane & 7, aw = lane >> 3;
  const uint32_t aBase = sb + G1_OFF_A + (mrow0 + lr + (aw & 1)*8)*(PADC*2) + ((aw >> 1)*8)*2;
  const uint32_t bBase = sb + G1_OFF_W + (ncol0 + ((lane >> 4) << 3) + lr)*(PADC*2) + (((lane >> 3) & 1)*8)*2;

  float acc[32];
  #pragma unroll
  for(int i=0;i<32;i++) acc[i] = 0.f;

  #pragma unroll
  for(int ks=0; ks<8; ks++){
    const uint32_t ko = ks*32;
    uint32_t aH[4];
    LDSM4(aH, aBase + ko);
    #pragma unroll
    for(int ntp=0; ntp<4; ntp++){
      uint32_t bH[4];
      LDSM4(bH, bBase + ntp*16*(PADC*2) + ko);
      mma16816(acc + (2*ntp  )*4, aH, bH);
      mma16816(acc + (2*ntp+1)*4, aH, bH+2);
    }
  }

  const float* sbias = reinterpret_cast<const float*>(smem + G1_OFF_BIAS);
  #pragma unroll
  for(int half=0; half<2; half++){
    const int R = tile*128 + mrow0 + g + half*8;
    if(R >= rows) continue;
    int n, m; row_to_nm(R, N, n, m);
    __half2* po16 = reinterpret_cast<__half2*>(out16 + ((size_t)n*MTOT + m)*CCH + ncol0);
    #pragma unroll
    for(int nt=0; nt<8; nt++){
      const int c0 = nt*8 + 2*t;
      float v0 = acc[nt*4 + half*2 + 0];
      float v1 = acc[nt*4 + half*2 + 1];
      if(m == 0){ v0 += sbias[ncol0 + c0]; v1 += sbias[ncol0 + c0 + 1]; }
      po16[c0 >> 1] = __floats2half2_rn(v0, v1);
    }
  }
}

// ======================================================================
// GEMM2: two-term split-A ((A_hi + A_lo) * W_hi), pre-split planes,
// pure cp.async staging. [R10 version]
// ======================================================================
#define G2_OFF_AH 0
#define G2_OFF_AL (128*PADC*2)            // 34816
#define G2_OFF_W  (2*128*PADC*2)          // 69632
#define G2_OFF_BIAS (3*128*PADC*2)        // 104448
#define G2_SMEM (G2_OFF_BIAS + 512)       // 104960

__global__ __launch_bounds__(512, 2)
void gemm2_kernel(const __half* __restrict__ Ahi, const __half* __restrict__ Alo,
                  const __half* __restrict__ Whi, const float* __restrict__ bias,
                  float* __restrict__ out, int N)
{
  extern __shared__ char smem[];
  const uint32_t sb = smem_u32(smem);
  const int tid = threadIdx.x;
  const int wid = tid >> 5, lane = tid & 31;
  const int tile = blockIdx.x;
  const int rows = 9*N;
  const int t0 = N >> 7, t1 = t0*4;
  const int l = (tile < t0) ? 0 : ((tile < t1) ? 1 : 2);

  { // async stage: W[l] + A hi/lo planes (all contiguous copies)
    const char* srcW = (const char*)(Whi + (size_t)l*CCH*CCH);
    const char* srcH = (const char*)(Ahi + (size_t)tile*128*CCH);
    const char* srcL = (const char*)(Alo + (size_t)tile*128*CCH);
    #pragma unroll
    for(int i=0;i<4;i++){
      int j = tid + i*512;                 // 2048 chunks = 128 rows x 16
      int row = j >> 4, chunk = j & 15;
      CP_ASYNC16(sb + G2_OFF_W  + row*(PADC*2) + chunk*16, srcW + row*256 + chunk*16);
      CP_ASYNC16(sb + G2_OFF_AH + row*(PADC*2) + chunk*16, srcH + row*256 + chunk*16);
      CP_ASYNC16(sb + G2_OFF_AL + row*(PADC*2) + chunk*16, srcL + row*256 + chunk*16);
    }
    asm volatile("cp.async.commit_group;");
  }
  if(tid < 128) *reinterpret_cast<float*>(smem + G2_OFF_BIAS + tid*4) = bias[tid];
  asm volatile("cp.async.wait_group 0;");
  __syncthreads();

  const int mrow0 = (wid >> 1)*16, ncol0 = (wid & 1)*64;
  const int g = lane >> 2, t = lane & 3;
  const int lr = lane & 7, aw = lane >> 3;
  const uint32_t aoff = (mrow0 + lr + (aw & 1)*8)*(PADC*2) + ((aw >> 1)*8)*2;
  const uint32_t aHBase = sb + G2_OFF_AH + aoff;
  const uint32_t aLBase = sb + G2_OFF_AL + aoff;
  const uint32_t bBase  = sb + G2_OFF_W + (ncol0 + ((lane >> 4) << 3) + lr)*(PADC*2) + (((lane >> 3) & 1)*8)*2;

  float acc[32];
  #pragma unroll
  for(int i=0;i<32;i++) acc[i] = 0.f;

  #pragma unroll
  for(int ks=0; ks<8; ks++){
    const uint32_t ko = ks*32;
    uint32_t aH[4], aL[4];
    LDSM4(aH, aHBase + ko);
    LDSM4(aL, aLBase + ko);
    #pragma unroll
    for(int ntp=0; ntp<4; ntp++){
      uint32_t bH[4];
      LDSM4(bH, bBase + ntp*16*(PADC*2) + ko);
      mma16816(acc + (2*ntp  )*4, aH, bH);
      mma16816(acc + (2*ntp  )*4, aL, bH);
      mma16816(acc + (2*ntp+1)*4, aH, bH+2);
      mma16816(acc + (2*ntp+1)*4, aL, bH+2);
    }
  }

  const float* sbias = reinterpret_cast<const float*>(smem + G2_OFF_BIAS);
  #pragma unroll
  for(int half=0; half<2; half++){
    const int R = tile*128 + mrow0 + g + half*8;
    if(R >= rows) continue;
    int n, m; row_to_nm(R, N, n, m);
    float pn = (m==0) ? 1.0f : ((m<4) ? 0.57735026918962576f : 0.70710678118654752f);
    float* po = out + ((size_t)n*MTOT + m)*CCH + ncol0;
    #pragma unroll
    for(int nt=0; nt<8; nt++){
      const int c0 = nt*8 + 2*t;
      float v0 = acc[nt*4 + half*2 + 0];
      float v1 = acc[nt*4 + half*2 + 1];
      if(m == 0){ v0 += sbias[ncol0 + c0]; v1 += sbias[ncol0 + c0 + 1]; }
      *reinterpret_cast<float2*>(po + c0) = make_float2(v0*pn, v1*pn);
    }
  }
}

// ======================================================================
// Device: contract accumulated outer-product tensor P with w3j + tpw.
// ======================================================================
__device__ __forceinline__ void contract_point(const float* p0, const float* p1, const float* p2,
                                               const float* tpw, const W3J& w, float* o){
  #pragma unroll
  for(int m=0;m<MTOT;m++) o[m]=0.0f;
  #pragma unroll
  for(int c=0;c<3;c++){
    float t=0.f;
    #pragma unroll
    for(int b=0;b<3;b++) t = fmaf(w.v[0 + b*3 + c], p0[b], t);
    o[1+c] = fmaf(tpw[0], t, o[1+c]);
  }
  {
    float t=0.f;
    #pragma unroll
    for(int a=0;a<3;a++)
      #pragma unroll
      for(int b=0;b<3;b++) t = fmaf(w.v[9 + a*3 + b], p1[a*3+b], t);
    o[0] = fmaf(tpw[1], t, o[0]);
  }
  #pragma unroll
  for(int c=0;c<3;c++){
    float t=0.f;
    #pragma unroll
    for(int a=0;a<3;a++)
      #pragma unroll
      for(int b=0;b<3;b++) t = fmaf(w.v[18 + (a*3+b)*3 + c], p1[a*3+b], t);
    o[1+c] = fmaf(tpw[2], t, o[1+c]);
  }
  #pragma unroll
  for(int c=0;c<5;c++){
    float t=0.f;
    #pragma unroll
    for(int a=0;a<3;a++)
      #pragma unroll
      for(int b=0;b<3;b++) t = fmaf(w.v[45 + (a*3+b)*5 + c], p1[a*3+b], t);
    o[4+c] = fmaf(tpw[3], t, o[4+c]);
  }
  #pragma unroll
  for(int c=0;c<3;c++){
    float t=0.f;
    #pragma unroll
    for(int a=0;a<5;a++)
      #pragma unroll
      for(int b=0;b<3;b++) t = fmaf(w.v[90 + (a*3+b)*3 + c], p2[a*3+b], t);
    o[1+c] = fmaf(tpw[4], t, o[1+c]);
  }
  #pragma unroll
  for(int c=0;c<5;c++){
    float t=0.f;
    #pragma unroll
    for(int a=0;a<5;a++)
      #pragma unroll
      for(int b=0;b<3;b++) t = fmaf(w.v[135 + (a*3+b)*5 + c], p2[a*3+b], t);
    o[4+c] = fmaf(tpw[5], t, o[4+c]);
  }
}

// ======================================================================
// Fully fused gather (R10 shape), packed epos4 + deeper unroll:
//   o[b] = contract(w3j, sum_j a_j * h1[n_j] (x) (y_b - ey_{n_j})) . tpw
// 2 channels/thread, 64 thr/node, 4 nodes/block; writes split-fp16 planes.
// ======================================================================
__global__ __launch_bounds__(256)
void gather_kernel(const __half* __restrict__ h1f,
                   const float* __restrict__ pos, const float4* __restrict__ epos4,
                   const float* __restrict__ alpha, const int* __restrict__ idx,
                   const float* __restrict__ tp_w,
                   __half* __restrict__ cdhi, __half* __restrict__ cdlo,
                   int N1, W3J w, float scale)
{
  const int b = blockIdx.x*4 + (threadIdx.x >> 6);
  if(b >= N1) return;
  const int t = threadIdx.x & 63;
  const int c0 = 2*t;
  const int h = c0 >> 4;

  float2 P[MTOT][3];
  #pragma unroll
  for(int m=0;m<MTOT;m++)
    #pragma unroll
    for(int k=0;k<3;k++) P[m][k] = make_float2(0.f, 0.f);

  float yb[3];
  #pragma unroll
  for(int k=0;k<3;k++) yb[k] = scale * pos[b*3+k];

  const int*   ib = idx   + (size_t)b*KNB;
  const float* ab = alpha + (size_t)b*KNB*HH;

  #pragma unroll 4
  for(int j=0;j<KNB;j++){
    const int n = ib[j];
    const float a = ab[j*HH + h];
    const float4 ep = epos4[n];
    float ady[3];
    ady[0] = a * (yb[0] - ep.x);
    ady[1] = a * (yb[1] - ep.y);
    ady[2] = a * (yb[2] - ep.z);
    const __half2* px = reinterpret_cast<const __half2*>(h1f + (size_t)n*MTOT*CCH) + t;
    #pragma unroll
    for(int m=0;m<MTOT;m++){
      float2 v = __half22float2(px[m*64]);
      #pragma unroll
      for(int k=0;k<3;k++){
        P[m][k].x = fmaf(v.x, ady[k], P[m][k].x);
        P[m][k].y = fmaf(v.y, ady[k], P[m][k].y);
      }
    }
  }

  float tpw0[6], tpw1[6];
  #pragma unroll
  for(int p=0;p<6;p++){
    float2 v = *reinterpret_cast<const float2*>(tp_w + p*CCH + c0);
    tpw0[p] = v.x; tpw1[p] = v.y;
  }

  float p0[3], p1[9], p2[15], o0[MTOT], o1[MTOT];
  #pragma unroll
  for(int k=0;k<3;k++) p0[k] = P[0][k].x;
  #pragma unroll
  for(int a2=0;a2<3;a2++)
    #pragma unroll
    for(int k=0;k<3;k++) p1[a2*3+k] = P[1+a2][k].x;
  #pragma unroll
  for(int a2=0;a2<5;a2++)
    #pragma unroll
    for(int k=0;k<3;k++) p2[a2*3+k] = P[4+a2][k].x;
  contract_point(p0, p1, p2, tpw0, w, o0);
  #pragma unroll
  for(int k=0;k<3;k++) p0[k] = P[0][k].y;
  #pragma unroll
  for(int a2=0;a2<3;a2++)
    #pragma unroll
    for(int k=0;k<3;k++) p1[a2*3+k] = P[1+a2][k].y;
  #pragma unroll
  for(int a2=0;a2<5;a2++)
    #pragma unroll
    for(int k=0;k<3;k++) p2[a2*3+k] = P[4+a2][k].y;
  contract_point(p0, p1, p2, tpw1, w, o1);

  // write split-fp16 planes in GEMM-row layout (half2 per plane per m)
  #pragma unroll
  for(int m=0;m<MTOT;m++){
    int R = (m==0) ? b : ((m<4) ? (N1 + b*3 + (m-1)) : (4*N1 + b*5 + (m-4)));
    __half2 hi2 = __floats2half2_rn(o0[m], o1[m]);
    float2 hf = __half22float2(hi2);
    __half2 lo2 = __floats2half2_rn(o0[m] - hf.x, o1[m] - hf.y);
    *reinterpret_cast<__half2*>(cdhi + (size_t)R*CCH + c0) = hi2;
    *reinterpret_cast<__half2*>(cdlo + (size_t)R*CCH + c0) = lo2;
  }
}

// ======================================================================
// launch
// ======================================================================
extern "C" void kernel_launch(void* const* d_in, const int* in_sizes, int n_in,
                              void* d_out, int out_size)
{
  const float* pos     = (const float*)d_in[0];
  const float* exp_pos = (const float*)d_in[1];
  // d_in[2] = h : unused by the reference
  const float* exp_h   = (const float*)d_in[3];
  const float* alpha   = (const float*)d_in[4];
  const int*   idx     = (const int*)  d_in[5];
  const float* w1w     = (const float*)d_in[6];
  const float* w1b     = (const float*)d_in[7];
  const float* w2w     = (const float*)d_in[8];
  const float* w2b     = (const float*)d_in[9];
  const float* tpw     = (const float*)d_in[10];

  const int N1 = in_sizes[0]/3;
  const int N2 = in_sizes[1]/3;

  W3J w;
  build_w3j(&w);
  const double PI = 3.14159265358979323846;
  const float scale = (float)(2.04665350914 * std::sqrt(3.0/(4.0*PI)));  // COEF1 * SH1_INT

  __half *p_h1f=nullptr, *p_whi=nullptr, *p_cdh=nullptr, *p_cdl=nullptr;
  float4* p_ep4=nullptr;
  cudaGetSymbolAddress((void**)&p_h1f, g_h1f16);
  cudaGetSymbolAddress((void**)&p_whi, g_Whi);
  cudaGetSymbolAddress((void**)&p_cdh, g_cdhi);
  cudaGetSymbolAddress((void**)&p_cdl, g_cdlo);
  cudaGetSymbolAddress((void**)&p_ep4, g_epos4);

  cudaFuncSetAttribute(gemm1_kernel, cudaFuncAttributeMaxDynamicSharedMemorySize, G1_SMEM);
  cudaFuncSetAttribute(gemm2_kernel, cudaFuncAttributeMaxDynamicSharedMemorySize, G2_SMEM);

  const int tiles2 = (9*N2 + 127) >> 7;   // 288 for N2=4096
  const int tiles1 = (9*N1 + 127) >> 7;

  // 0) W images + packed scaled exp_pos
  conv_w_kernel<<<(2*3*CCH*CCH + 255)/256, 256>>>(w1w, w2w, p_whi, exp_pos, p_ep4, N2, scale);
  // 1) h1f16 = fp16( so3_linear(exp_h, w1) )
  gemm1_kernel<<<tiles2, 512, G1_SMEM>>>(exp_h, p_whi, w1b, p_h1f, N2);
  // 2) fused gather -> split-fp16 planes in GEMM-row layout
  gather_kernel<<<(N1+3)/4, 256>>>(p_h1f, pos, p_ep4, alpha, idx, tpw, p_cdh, p_cdl, N1, w, scale);
  // 3) out = so3_linear(cdiff, w2) * PATH_NORM
  gemm2_kernel<<<tiles1, 512, G2_SMEM>>>(p_cdh, p_cdl, p_whi + 3*CCH*CCH, w2b, (float*)d_out, N1);
}

// round 15
// speedup vs baseline: 1.2892x; 1.0824x over previous
#include <cuda_runtime.h>
#include <cuda_fp16.h>
#include <cmath>
#include <complex>
#include <algorithm>
#include <cstdint>

// ---------------- problem constants ----------------
#define MTOT 9        // (LMAX+1)^2
#define CCH  128      // channels
#define KNB  16       // neighbors
#define HH   8        // heads
#define MAXN 4096     // max nodes (matches setup)

struct W3J { float v[210]; };

// ---------------- scratch (static device globals; no allocation) ----------------
__device__ __half g_h1f16[MAXN * MTOT * CCH];      // fp16 gather payload [n][m][c]
__device__ __half g_cdhi [MAXN * MTOT * CCH];      // gather output fp16, GEMM-row layout
__device__ __half g_Whi[2 * 3 * CCH * CCH];        // transposed: [which][l][d_out][c_in]
__device__ float4 g_epos4[MAXN];                   // scale * exp_pos, packed

// ======================================================================
// Host-side real Wigner-3j construction (port of the e3nn-style reference)
// ======================================================================
static double hfact(int n){ double r=1.0; for(int i=2;i<=n;i++) r*= (double)i; return r; }

static double su2_cg(int j1,int j2,int j3,int m1,int m2,int m3){
  if(m3 != m1+m2) return 0.0;
  if(j3 < std::abs(j1-j2) || j3 > j1+j2) return 0.0;
  double pref = std::sqrt((2.0*j3+1.0)*hfact(j1+j2-j3)*hfact(j1-j2+j3)*hfact(-j1+j2+j3)/hfact(j1+j2+j3+1));
  pref *= std::sqrt(hfact(j3+m3)*hfact(j3-m3)*hfact(j1-m1)*hfact(j1+m1)*hfact(j2-m2)*hfact(j2+m2));
  int vmin = std::max(0, std::max(j2-j3-m1, j1-j3+m2));
  int vmax = std::min(j1+j2-j3, std::min(j1-m1, j2+m2));
  double s=0.0;
  for(int v=vmin; v<=vmax; v++){
    double den = hfact(v)*hfact(j1+j2-j3-v)*hfact(j1-m1-v)*hfact(j2+m2-v)*hfact(j3-j2+m1+v)*hfact(j3-j1-m2+v);
    s += ((v&1)? -1.0 : 1.0)/den;
  }
  return pref*s;
}

static void q_r2c(int l, std::complex<double>* q){
  int n = 2*l+1;
  for(int i=0;i<n*n;i++) q[i]=std::complex<double>(0.0,0.0);
  double is2 = 1.0/std::sqrt(2.0);
  for(int m=-l;m<0;m++){
    q[(l+m)*n + (l-m)] = std::complex<double>(is2, 0.0);
    q[(l+m)*n + (l+m)] = std::complex<double>(0.0,-is2);
  }
  q[l*n + l] = std::complex<double>(1.0,0.0);
  for(int m=1;m<=l;m++){
    double sg = (m&1)? -1.0 : 1.0;
    q[(l+m)*n + (l+m)] = std::complex<double>(sg*is2, 0.0);
    q[(l+m)*n + (l-m)] = std::complex<double>(0.0, sg*is2);
  }
  std::complex<double> f(1.0,0.0), mi(0.0,-1.0);
  for(int i=0;i<l;i++) f *= mi;
  for(int i=0;i<n*n;i++) q[i] *= f;
}

static void real_w3j(int l1, int l3, float* out){
  const int n1=2*l1+1, n2=3, n3=2*l3+1;
  std::complex<double> Cc[5*3*5];
  for(int i=0;i<n1;i++) for(int j=0;j<n2;j++) for(int k=0;k<n3;k++)
    Cc[(i*n2+j)*n3+k] = std::complex<double>(su2_cg(l1,1,l3, i-l1, j-1, k-l3), 0.0);
  std::complex<double> Q1[25],Q2[9],Q3[25];
  q_r2c(l1,Q1); q_r2c(1,Q2); q_r2c(l3,Q3);
  std::complex<double> C[5*3*5];
  for(int a=0;a<n1;a++) for(int b=0;b<n2;b++) for(int c=0;c<n3;c++){
    std::complex<double> s(0.0,0.0);
    for(int i=0;i<n1;i++) for(int j=0;j<n2;j++) for(int k=0;k<n3;k++)
      s += Q1[i*n1+a]*Q2[j*n2+b]*std::conj(Q3[k*n3+c])*Cc[(i*n2+j)*n3+k];
    C[(a*n2+b)*n3+c]=s;
  }
  double sr=0.0, si=0.0;
  for(int i=0;i<n1*n2*n3;i++){ sr += std::fabs(C[i].real()); si += std::fabs(C[i].imag()); }
  double vals[75]; double norm=0.0;
  for(int i=0;i<n1*n2*n3;i++){ double v=(sr>=si)? C[i].real() : C[i].imag(); vals[i]=v; norm+=v*v; }
  norm = std::sqrt(norm);
  double sc = std::sqrt((double)(2*l3+1))/norm;
  for(int i=0;i<n1*n2*n3;i++) out[i] = (float)(vals[i]*sc);
}

static void build_w3j(W3J* w){
  real_w3j(0,1, w->v+0);
  real_w3j(1,0, w->v+9);
  real_w3j(1,1, w->v+18);
  real_w3j(1,2, w->v+45);
  real_w3j(2,1, w->v+90);
  real_w3j(2,2, w->v+135);
}

// ======================================================================
// Row mapping: GEMM rows grouped by degree.
// ======================================================================
__device__ __forceinline__ void row_to_nm(int R, int N, int& n, int& m){
  if(R < N){ n = R; m = 0; }
  else if(R < 4*N){ int q = R - N; n = q/3; m = 1 + q%3; }
  else { int q = R - 4*N; n = q/5; m = 4 + q%5; }
}

__device__ __forceinline__ uint32_t smem_u32(const void* p){
  uint32_t a;
  asm("{ .reg .u64 t; cvta.to.shared.u64 t, %1; cvt.u32.u64 %0, t; }" : "=r"(a) : "l"(p));
  return a;
}

// ======================================================================
// W conversion + scaled exp_pos packing
// ======================================================================
__global__ __launch_bounds__(256)
void conv_w_kernel(const float* __restrict__ w1, const float* __restrict__ w2,
                   __half* __restrict__ Whi,
                   const float* __restrict__ exp_pos, float4* __restrict__ epos4,
                   int N2, float scale)
{
  int t = blockIdx.x*256 + threadIdx.x;
  if(t < N2){
    epos4[t] = make_float4(scale*exp_pos[t*3+0], scale*exp_pos[t*3+1], scale*exp_pos[t*3+2], 0.f);
  }
  if(t >= 2*3*CCH*CCH) return;
  int which = t / (3*CCH*CCH);
  int rem = t % (3*CCH*CCH);
  int l = rem / (CCH*CCH);
  int e = rem % (CCH*CCH);
  int d = e >> 7, c = e & 127;
  const float* w = which ? w2 : w1;
  Whi[t] = __float2half_rn(w[((size_t)l*CCH + c)*CCH + d]);
}

// ======================================================================
// HMMA GEMM common pieces
// ======================================================================
#define PADC 136                        // padded smem row stride in halves (272B)

__device__ __forceinline__ void mma16816(float* c, const uint32_t* a, const uint32_t* b){
  asm volatile("mma.sync.aligned.m16n8k16.row.col.f32.f16.f16.f32 "
               "{%0,%1,%2,%3}, {%4,%5,%6,%7}, {%8,%9}, {%0,%1,%2,%3};"
               : "+f"(c[0]), "+f"(c[1]), "+f"(c[2]), "+f"(c[3])
               : "r"(a[0]), "r"(a[1]), "r"(a[2]), "r"(a[3]), "r"(b[0]), "r"(b[1]));
}

#define LDSM4(r, addr) \
  asm volatile("ldmatrix.sync.aligned.m8n8.x4.shared.b16 {%0,%1,%2,%3}, [%4];" \
               : "=r"((r)[0]), "=r"((r)[1]), "=r"((r)[2]), "=r"((r)[3]) : "r"(addr))

#define CP_ASYNC16(dst, src) \
  asm volatile("cp.async.ca.shared.global [%0], [%1], 16;" :: "r"(dst), "l"(src))

// ======================================================================
// GEMM1: single-term fp16 (A_hi * W_hi), output fp16 only. [R10 version]
// ======================================================================
#define G1_OFF_A 0
#define G1_OFF_W (128*PADC*2)            // 34816
#define G1_OFF_BIAS (2*128*PADC*2)       // 69632
#define G1_SMEM (G1_OFF_BIAS + 512)      // 70144

__global__ __launch_bounds__(512, 2)
void gemm1_kernel(const float* __restrict__ x, const __half* __restrict__ Whi,
                  const float* __restrict__ bias, __half* __restrict__ out16, int N)
{
  extern __shared__ char smem[];
  const uint32_t sb = smem_u32(smem);
  const int tid = threadIdx.x;
  const int wid = tid >> 5, lane = tid & 31;
  const int tile = blockIdx.x;
  const int rows = 9*N;
  const int t0 = N >> 7, t1 = t0*4;
  const int l = (tile < t0) ? 0 : ((tile < t1) ? 1 : 2);

  { // async stage W[l]
    const char* srcH = (const char*)(Whi + (size_t)l*CCH*CCH);
    #pragma unroll
    for(int i=0;i<4;i++){
      int j = tid + i*512;
      int row = j >> 4, chunk = j & 15;
      CP_ASYNC16(sb + G1_OFF_W + row*(PADC*2) + chunk*16, srcH + row*256 + chunk*16);
    }
    asm volatile("cp.async.commit_group;");
  }
  if(tid < 128) *reinterpret_cast<float*>(smem + G1_OFF_BIAS + tid*4) = bias[tid];

  // stage A (fp32 -> fp16 hi, padded)
  #pragma unroll
  for(int i=0;i<8;i++){
    int j = tid + i*512;
    int row = j >> 5, col4 = j & 31;
    int R = tile*128 + row;
    float4 v = make_float4(0.f,0.f,0.f,0.f);
    if(R < rows){
      int n, m; row_to_nm(R, N, n, m);
      v = reinterpret_cast<const float4*>(x)[ ((size_t)n*MTOT + m)*32 + col4 ];
    }
    uint2 hp;
    hp.x = __half_as_ushort(__float2half_rn(v.x)) | ((uint32_t)__half_as_ushort(__float2half_rn(v.y)) << 16);
    hp.y = __half_as_ushort(__float2half_rn(v.z)) | ((uint32_t)__half_as_ushort(__float2half_rn(v.w)) << 16);
    *reinterpret_cast<uint2*>(smem + G1_OFF_A + row*(PADC*2) + col4*8) = hp;
  }
  asm volatile("cp.async.wait_group 0;");
  __syncthreads();

  const int mrow0 = (wid >> 1)*16, ncol0 = (wid & 1)*64;
  const int g = lane >> 2, t = lane & 3;
  const int lr = lane & 7, aw = lane >> 3;
  const uint32_t aBase = sb + G1_OFF_A + (mrow0 + lr + (aw & 1)*8)*(PADC*2) + ((aw >> 1)*8)*2;
  const uint32_t bBase = sb + G1_OFF_W + (ncol0 + ((lane >> 4) << 3) + lr)*(PADC*2) + (((lane >> 3) & 1)*8)*2;

  float acc[32];
  #pragma unroll
  for(int i=0;i<32;i++) acc[i] = 0.f;

  #pragma unroll
  for(int ks=0; ks<8; ks++){
    const uint32_t ko = ks*32;
    uint32_t aH[4];
    LDSM4(aH, aBase + ko);
    #pragma unroll
    for(int ntp=0; ntp<4; ntp++){
      uint32_t bH[4];
      LDSM4(bH, bBase + ntp*16*(PADC*2) + ko);
      mma16816(acc + (2*ntp  )*4, aH, bH);
      mma16816(acc + (2*ntp+1)*4, aH, bH+2);
    }
  }

  const float* sbias = reinterpret_cast<const float*>(smem + G1_OFF_BIAS);
  #pragma unroll
  for(int half=0; half<2; half++){
    const int R = tile*128 + mrow0 + g + half*8;
    if(R >= rows) continue;
    int n, m; row_to_nm(R, N, n, m);
    __half2* po16 = reinterpret_cast<__half2*>(out16 + ((size_t)n*MTOT + m)*CCH + ncol0);
    #pragma unroll
    for(int nt=0; nt<8; nt++){
      const int c0 = nt*8 + 2*t;
      float v0 = acc[nt*4 + half*2 + 0];
      float v1 = acc[nt*4 + half*2 + 1];
      if(m == 0){ v0 += sbias[ncol0 + c0]; v1 += sbias[ncol0 + c0 + 1]; }
      po16[c0 >> 1] = __floats2half2_rn(v0, v1);
    }
  }
}

// ======================================================================
// GEMM2: single-term fp16 (A * W_hi), A pre-converted fp16 in GEMM-row
// layout -> pure cp.async staging. Output fp32 + bias + PATH_NORM.
// ======================================================================
#define G2_OFF_A 0
#define G2_OFF_W (128*PADC*2)            // 34816
#define G2_OFF_BIAS (2*128*PADC*2)       // 69632
#define G2_SMEM (G2_OFF_BIAS + 512)      // 70144

__global__ __launch_bounds__(512, 2)
void gemm2_kernel(const __half* __restrict__ Ahi, const __half* __restrict__ Whi,
                  const float* __restrict__ bias, float* __restrict__ out, int N)
{
  extern __shared__ char smem[];
  const uint32_t sb = smem_u32(smem);
  const int tid = threadIdx.x;
  const int wid = tid >> 5, lane = tid & 31;
  const int tile = blockIdx.x;
  const int rows = 9*N;
  const int t0 = N >> 7, t1 = t0*4;
  const int l = (tile < t0) ? 0 : ((tile < t1) ? 1 : 2);

  { // async stage: W[l] + A plane (contiguous copies)
    const char* srcW = (const char*)(Whi + (size_t)l*CCH*CCH);
    const char* srcA = (const char*)(Ahi + (size_t)tile*128*CCH);
    #pragma unroll
    for(int i=0;i<4;i++){
      int j = tid + i*512;                 // 2048 chunks = 128 rows x 16
      int row = j >> 4, chunk = j & 15;
      CP_ASYNC16(sb + G2_OFF_W + row*(PADC*2) + chunk*16, srcW + row*256 + chunk*16);
      CP_ASYNC16(sb + G2_OFF_A + row*(PADC*2) + chunk*16, srcA + row*256 + chunk*16);
    }
    asm volatile("cp.async.commit_group;");
  }
  if(tid < 128) *reinterpret_cast<float*>(smem + G2_OFF_BIAS + tid*4) = bias[tid];
  asm volatile("cp.async.wait_group 0;");
  __syncthreads();

  const int mrow0 = (wid >> 1)*16, ncol0 = (wid & 1)*64;
  const int g = lane >> 2, t = lane & 3;
  const int lr = lane & 7, aw = lane >> 3;
  const uint32_t aBase = sb + G2_OFF_A + (mrow0 + lr + (aw & 1)*8)*(PADC*2) + ((aw >> 1)*8)*2;
  const uint32_t bBase = sb + G2_OFF_W + (ncol0 + ((lane >> 4) << 3) + lr)*(PADC*2) + (((lane >> 3) & 1)*8)*2;

  float acc[32];
  #pragma unroll
  for(int i=0;i<32;i++) acc[i] = 0.f;

  #pragma unroll
  for(int ks=0; ks<8; ks++){
    const uint32_t ko = ks*32;
    uint32_t aH[4];
    LDSM4(aH, aBase + ko);
    #pragma unroll
    for(int ntp=0; ntp<4; ntp++){
      uint32_t bH[4];
      LDSM4(bH, bBase + ntp*16*(PADC*2) + ko);
      mma16816(acc + (2*ntp  )*4, aH, bH);
      mma16816(acc + (2*ntp+1)*4, aH, bH+2);
    }
  }

  const float* sbias = reinterpret_cast<const float*>(smem + G2_OFF_BIAS);
  #pragma unroll
  for(int half=0; half<2; half++){
    const int R = tile*128 + mrow0 + g + half*8;
    if(R >= rows) continue;
    int n, m; row_to_nm(R, N, n, m);
    float pn = (m==0) ? 1.0f : ((m<4) ? 0.57735026918962576f : 0.70710678118654752f);
    float* po = out + ((size_t)n*MTOT + m)*CCH + ncol0;
    #pragma unroll
    for(int nt=0; nt<8; nt++){
      const int c0 = nt*8 + 2*t;
      float v0 = acc[nt*4 + half*2 + 0];
      float v1 = acc[nt*4 + half*2 + 1];
      if(m == 0){ v0 += sbias[ncol0 + c0]; v1 += sbias[ncol0 + c0 + 1]; }
      *reinterpret_cast<float2*>(po + c0) = make_float2(v0*pn, v1*pn);
    }
  }
}

// ======================================================================
// Device: contract accumulated outer-product tensor P with w3j + tpw.
// ======================================================================
__device__ __forceinline__ void contract_point(const float* p0, const float* p1, const float* p2,
                                               const float* tpw, const W3J& w, float* o){
  #pragma unroll
  for(int m=0;m<MTOT;m++) o[m]=0.0f;
  #pragma unroll
  for(int c=0;c<3;c++){
    float t=0.f;
    #pragma unroll
    for(int b=0;b<3;b++) t = fmaf(w.v[0 + b*3 + c], p0[b], t);
    o[1+c] = fmaf(tpw[0], t, o[1+c]);
  }
  {
    float t=0.f;
    #pragma unroll
    for(int a=0;a<3;a++)
      #pragma unroll
      for(int b=0;b<3;b++) t = fmaf(w.v[9 + a*3 + b], p1[a*3+b], t);
    o[0] = fmaf(tpw[1], t, o[0]);
  }
  #pragma unroll
  for(int c=0;c<3;c++){
    float t=0.f;
    #pragma unroll
    for(int a=0;a<3;a++)
      #pragma unroll
      for(int b=0;b<3;b++) t = fmaf(w.v[18 + (a*3+b)*3 + c], p1[a*3+b], t);
    o[1+c] = fmaf(tpw[2], t, o[1+c]);
  }
  #pragma unroll
  for(int c=0;c<5;c++){
    float t=0.f;
    #pragma unroll
    for(int a=0;a<3;a++)
      #pragma unroll
      for(int b=0;b<3;b++) t = fmaf(w.v[45 + (a*3+b)*5 + c], p1[a*3+b], t);
    o[4+c] = fmaf(tpw[3], t, o[4+c]);
  }
  #pragma unroll
  for(int c=0;c<3;c++){
    float t=0.f;
    #pragma unroll
    for(int a=0;a<5;a++)
      #pragma unroll
      for(int b=0;b<3;b++) t = fmaf(w.v[90 + (a*3+b)*3 + c], p2[a*3+b], t);
    o[1+c] = fmaf(tpw[4], t, o[1+c]);
  }
  #pragma unroll
  for(int c=0;c<5;c++){
    float t=0.f;
    #pragma unroll
    for(int a=0;a<5;a++)
      #pragma unroll
      for(int b=0;b<3;b++) t = fmaf(w.v[135 + (a*3+b)*5 + c], p2[a*3+b], t);
    o[4+c] = fmaf(tpw[5], t, o[4+c]);
  }
}

// ======================================================================
// Fully fused gather (R14 shape), single fp16 output plane:
//   o[b] = contract(w3j, sum_j a_j * h1[n_j] (x) (y_b - ey_{n_j})) . tpw
// ======================================================================
__global__ __launch_bounds__(256)
void gather_kernel(const __half* __restrict__ h1f,
                   const float* __restrict__ pos, const float4* __restrict__ epos4,
                   const float* __restrict__ alpha, const int* __restrict__ idx,
                   const float* __restrict__ tp_w,
                   __half* __restrict__ cdhi,
                   int N1, W3J w, float scale)
{
  const int b = blockIdx.x*4 + (threadIdx.x >> 6);
  if(b >= N1) return;
  const int t = threadIdx.x & 63;
  const int c0 = 2*t;
  const int h = c0 >> 4;

  float2 P[MTOT][3];
  #pragma unroll
  for(int m=0;m<MTOT;m++)
    #pragma unroll
    for(int k=0;k<3;k++) P[m][k] = make_float2(0.f, 0.f);

  float yb[3];
  #pragma unroll
  for(int k=0;k<3;k++) yb[k] = scale * pos[b*3+k];

  const int*   ib = idx   + (size_t)b*KNB;
  const float* ab = alpha + (size_t)b*KNB*HH;

  #pragma unroll 4
  for(int j=0;j<KNB;j++){
    const int n = ib[j];
    const float a = ab[j*HH + h];
    const float4 ep = epos4[n];
    float ady[3];
    ady[0] = a * (yb[0] - ep.x);
    ady[1] = a * (yb[1] - ep.y);
    ady[2] = a * (yb[2] - ep.z);
    const __half2* px = reinterpret_cast<const __half2*>(h1f + (size_t)n*MTOT*CCH) + t;
    #pragma unroll
    for(int m=0;m<MTOT;m++){
      float2 v = __half22float2(px[m*64]);
      #pragma unroll
      for(int k=0;k<3;k++){
        P[m][k].x = fmaf(v.x, ady[k], P[m][k].x);
        P[m][k].y = fmaf(v.y, ady[k], P[m][k].y);
      }
    }
  }

  float tpw0[6], tpw1[6];
  #pragma unroll
  for(int p=0;p<6;p++){
    float2 v = *reinterpret_cast<const float2*>(tp_w + p*CCH + c0);
    tpw0[p] = v.x; tpw1[p] = v.y;
  }

  float p0[3], p1[9], p2[15], o0[MTOT], o1[MTOT];
  #pragma unroll
  for(int k=0;k<3;k++) p0[k] = P[0][k].x;
  #pragma unroll
  for(int a2=0;a2<3;a2++)
    #pragma unroll
    for(int k=0;k<3;k++) p1[a2*3+k] = P[1+a2][k].x;
  #pragma unroll
  for(int a2=0;a2<5;a2++)
    #pragma unroll
    for(int k=0;k<3;k++) p2[a2*3+k] = P[4+a2][k].x;
  contract_point(p0, p1, p2, tpw0, w, o0);
  #pragma unroll
  for(int k=0;k<3;k++) p0[k] = P[0][k].y;
  #pragma unroll
  for(int a2=0;a2<3;a2++)
    #pragma unroll
    for(int k=0;k<3;k++) p1[a2*3+k] = P[1+a2][k].y;
  #pragma unroll
  for(int a2=0;a2<5;a2++)
    #pragma unroll
    for(int k=0;k<3;k++) p2[a2*3+k] = P[4+a2][k].y;
  contract_point(p0, p1, p2, tpw1, w, o1);

  // write single fp16 plane in GEMM-row layout
  #pragma unroll
  for(int m=0;m<MTOT;m++){
    int R = (m==0) ? b : ((m<4) ? (N1 + b*3 + (m-1)) : (4*N1 + b*5 + (m-4)));
    *reinterpret_cast<__half2*>(cdhi + (size_t)R*CCH + c0) = __floats2half2_rn(o0[m], o1[m]);
  }
}

// ======================================================================
// launch
// ======================================================================
extern "C" void kernel_launch(void* const* d_in, const int* in_sizes, int n_in,
                              void* d_out, int out_size)
{
  const float* pos     = (const float*)d_in[0];
  const float* exp_pos = (const float*)d_in[1];
  // d_in[2] = h : unused by the reference
  const float* exp_h   = (const float*)d_in[3];
  const float* alpha   = (const float*)d_in[4];
  const int*   idx     = (const int*)  d_in[5];
  const float* w1w     = (const float*)d_in[6];
  const float* w1b     = (const float*)d_in[7];
  const float* w2w     = (const float*)d_in[8];
  const float* w2b     = (const float*)d_in[9];
  const float* tpw     = (const float*)d_in[10];

  const int N1 = in_sizes[0]/3;
  const int N2 = in_sizes[1]/3;

  W3J w;
  build_w3j(&w);
  const double PI = 3.14159265358979323846;
  const float scale = (float)(2.04665350914 * std::sqrt(3.0/(4.0*PI)));  // COEF1 * SH1_INT

  __half *p_h1f=nullptr, *p_whi=nullptr, *p_cdh=nullptr;
  float4* p_ep4=nullptr;
  cudaGetSymbolAddress((void**)&p_h1f, g_h1f16);
  cudaGetSymbolAddress((void**)&p_whi, g_Whi);
  cudaGetSymbolAddress((void**)&p_cdh, g_cdhi);
  cudaGetSymbolAddress((void**)&p_ep4, g_epos4);

  cudaFuncSetAttribute(gemm1_kernel, cudaFuncAttributeMaxDynamicSharedMemorySize, G1_SMEM);
  cudaFuncSetAttribute(gemm2_kernel, cudaFuncAttributeMaxDynamicSharedMemorySize, G2_SMEM);

  const int tiles2 = (9*N2 + 127) >> 7;   // 288 for N2=4096
  const int tiles1 = (9*N1 + 127) >> 7;

  // 0) W images + packed scaled exp_pos
  conv_w_kernel<<<(2*3*CCH*CCH + 255)/256, 256>>>(w1w, w2w, p_whi, exp_pos, p_ep4, N2, scale);
  // 1) h1f16 = fp16( so3_linear(exp_h, w1) )
  gemm1_kernel<<<tiles2, 512, G1_SMEM>>>(exp_h, p_whi, w1b, p_h1f, N2);
  // 2) fused gather -> fp16 plane in GEMM-row layout
  gather_kernel<<<(N1+3)/4, 256>>>(p_h1f, pos, p_ep4, alpha, idx, tpw, p_cdh, N1, w, scale);
  // 3) out = so3_linear(cdiff, w2) * PATH_NORM  [single-term fp16]
  gemm2_kernel<<<tiles1, 512, G2_SMEM>>>(p_cdh, p_whi + 3*CCH*CCH, w2b, (float*)d_out, N1);
}